// round 12
// baseline (speedup 1.0000x reference)
#include <cuda_runtime.h>

// SwinMSA fused kernel — round 5: wavefront surgery.
// B=16, WN=4096, S=10, E=96, H=4, dh=24.  WPB=4 windows/CTA, 288 threads.
//   phase 1: qkv = X @ W_qkv + b   (4 strided cols x 10 rows, FFMA2, conflict-free scatter)
//   phase 2: attention, FFMA2-vectorized QK (k-pairs) and AV (d-pairs)
//   phase 3: out = ctx @ W_o + b_o (8 cols x 4 rows per thread, FFMA2)

#define S_    10
#define E_    96
#define H_    4
#define DH_   24
#define N3_   288
#define WPB   4
#define ROWS  (WPB * S_)      // 40
#define XS    48              // xt row stride (floats): X^T gapped rows (12/window), ctx flat
#define QR    10              // sQ/sK row-dim stride (gcd(10,32)=2 -> 2-way worst)
#define WN_   4096
#define NTHREADS 288

typedef unsigned long long u64;

__device__ __forceinline__ u64 fma2(u64 a, u64 b, u64 c) {
    u64 d; asm("fma.rn.f32x2 %0, %1, %2, %3;" : "=l"(d) : "l"(a), "l"(b), "l"(c)); return d;
}
__device__ __forceinline__ u64 mul2(u64 a, u64 b) {
    u64 d; asm("mul.rn.f32x2 %0, %1, %2;" : "=l"(d) : "l"(a), "l"(b)); return d;
}
__device__ __forceinline__ u64 dup2(float x) {
    u64 d; asm("mov.b64 %0, {%1, %1};" : "=l"(d) : "f"(x)); return d;
}
__device__ __forceinline__ void unpack2(u64 v, float& lo, float& hi) {
    asm("mov.b64 {%0, %1}, %2;" : "=f"(lo), "=f"(hi) : "l"(v));
}
__device__ __forceinline__ void lds_v2u64(u64& a, u64& b, const float* p) {
    unsigned addr = (unsigned)__cvta_generic_to_shared(p);
    asm volatile("ld.shared.v2.b64 {%0, %1}, [%2];" : "=l"(a), "=l"(b) : "r"(addr));
}
__device__ __forceinline__ u64 lds_u64(const float* p) {
    unsigned addr = (unsigned)__cvta_generic_to_shared(p);
    u64 a; asm volatile("ld.shared.b64 %0, [%1];" : "=l"(a) : "r"(addr)); return a;
}

__global__ __launch_bounds__(NTHREADS, 3)
void swin_msa_kernel(const float* __restrict__ X,
                     const float* __restrict__ Wqkv,
                     const float* __restrict__ bqkv,
                     const float* __restrict__ Wo,
                     const float* __restrict__ bo,
                     const float* __restrict__ posb,
                     float* __restrict__ out)
{
    __shared__ __align__(16) float xt[E_ * XS];            // X^T (gapped rows), then ctx^T (flat rows)
    __shared__ __align__(16) float sQ[16 * DH_ * QR];      // [wh][d][row]
    __shared__ __align__(16) float sK[16 * DH_ * QR];      // [wh][d][row]
    __shared__ __align__(16) float sV[16 * S_ * DH_];      // [wh][row][d]
    __shared__ float spb[(2 * S_ - 1) * H_];

    const int tid = threadIdx.x;
    const long wbase = (long)blockIdx.x * WPB;

    // ---- load X transposed: scattered LDG, conflict-free STS ----
    {
        const float4* gX4 = (const float4*)(X + wbase * (S_ * E_));
        for (int i = tid; i < ROWS * E_ / 4; i += NTHREADS) {
            const int r  = i % ROWS;                 // lanes: consecutive rows
            const int kq = i / ROWS;                 // k quad
            const float4 v = gX4[r * (E_ / 4) + kq];
            const int rs = (r / S_) * 12 + (r % S_); // gapped row slot
            float* p = xt + (4 * kq) * XS + rs;
            p[0] = v.x; p[XS] = v.y; p[2 * XS] = v.z; p[3 * XS] = v.w;
        }
        if (tid < (2 * S_ - 1) * H_) spb[tid] = posb[tid];
    }
    __syncthreads();

    // ---- phase 1: qkv projection. thread = 4 strided cols (cg+72j) x 10 rows ----
    {
        const int cg = tid % 72;
        const int rq = tid / 72;           // window index
        const int r0 = 12 * rq;            // gapped row-slot base

        u64 acc[4][5];
        #pragma unroll
        for (int j = 0; j < 4; j++) {
            const u64 b = dup2(bqkv[cg + 72 * j]);
            #pragma unroll
            for (int p = 0; p < 5; p++) acc[j][p] = b;
        }

        const float* wrow = Wqkv + cg;
        const float* xrow = xt + r0;

        #pragma unroll 2
        for (int k = 0; k < E_; k++) {
            const float* wk = wrow + k * N3_;
            const u64 w0 = dup2(wk[0]);
            const u64 w1 = dup2(wk[72]);
            const u64 w2 = dup2(wk[144]);
            const u64 w3 = dup2(wk[216]);
            const float* xk = xrow + k * XS;
            u64 x0, x1, x2, x3, x4;
            lds_v2u64(x0, x1, xk);
            lds_v2u64(x2, x3, xk + 4);
            x4 = lds_u64(xk + 8);
            acc[0][0] = fma2(x0, w0, acc[0][0]); acc[0][1] = fma2(x1, w0, acc[0][1]);
            acc[0][2] = fma2(x2, w0, acc[0][2]); acc[0][3] = fma2(x3, w0, acc[0][3]);
            acc[0][4] = fma2(x4, w0, acc[0][4]);
            acc[1][0] = fma2(x0, w1, acc[1][0]); acc[1][1] = fma2(x1, w1, acc[1][1]);
            acc[1][2] = fma2(x2, w1, acc[1][2]); acc[1][3] = fma2(x3, w1, acc[1][3]);
            acc[1][4] = fma2(x4, w1, acc[1][4]);
            acc[2][0] = fma2(x0, w2, acc[2][0]); acc[2][1] = fma2(x1, w2, acc[2][1]);
            acc[2][2] = fma2(x2, w2, acc[2][2]); acc[2][3] = fma2(x3, w2, acc[2][3]);
            acc[2][4] = fma2(x4, w2, acc[2][4]);
            acc[3][0] = fma2(x0, w3, acc[3][0]); acc[3][1] = fma2(x1, w3, acc[3][1]);
            acc[3][2] = fma2(x2, w3, acc[3][2]); acc[3][3] = fma2(x3, w3, acc[3][3]);
            acc[3][4] = fma2(x4, w3, acc[3][4]);
        }

        const u64 sc2 = dup2(0.20412414523193154f);   // 24^-0.5
        #pragma unroll
        for (int j = 0; j < 4; j++) {
            const int c = cg + 72 * j;
            const int pp = c / E_;                    // 0=q 1=k 2=v
            const int rem = c - pp * E_;
            const int h = rem / DH_;
            const int d = rem - h * DH_;
            const int wh = rq * H_ + h;
            if (pp == 0) {
                u64* dst = (u64*)&sQ[(wh * DH_ + d) * QR];
                #pragma unroll
                for (int p = 0; p < 5; p++) dst[p] = mul2(acc[j][p], sc2);
            } else if (pp == 1) {
                u64* dst = (u64*)&sK[(wh * DH_ + d) * QR];
                #pragma unroll
                for (int p = 0; p < 5; p++) dst[p] = acc[j][p];
            } else {
                float* dst = &sV[wh * S_ * DH_ + d];
                #pragma unroll
                for (int p = 0; p < 5; p++) {
                    float lo, hi; unpack2(acc[j][p], lo, hi);
                    dst[(2 * p) * DH_]     = lo;
                    dst[(2 * p + 1) * DH_] = hi;
                }
            }
        }
    }
    __syncthreads();

    // ---- phase 2: attention, thread = (wh, q); FFMA2 over k-pairs and d-pairs ----
    if (tid < 16 * S_) {
        const int wh = tid / S_;           // wi*4 + h
        const int q  = tid - wh * S_;
        const int wi = wh >> 2;
        const int h  = wh & 3;

        float qv[DH_];
        #pragma unroll
        for (int d = 0; d < DH_; d++) qv[d] = sQ[(wh * DH_ + d) * QR + q];

        u64 s2[5];
        #pragma unroll
        for (int p = 0; p < 5; p++) s2[p] = 0ull;
        #pragma unroll
        for (int d = 0; d < DH_; d++) {
            const u64 qd = dup2(qv[d]);
            const u64* kr = (const u64*)&sK[(wh * DH_ + d) * QR];
            #pragma unroll
            for (int p = 0; p < 5; p++) s2[p] = fma2(kr[p], qd, s2[p]);
        }

        const bool masked = (((wbase + wi) & (WN_ - 1)) == (WN_ - 1));
        float row[S_];
        #pragma unroll
        for (int p = 0; p < 5; p++) unpack2(s2[p], row[2 * p], row[2 * p + 1]);
        #pragma unroll
        for (int kk = 0; kk < S_; kk++) {
            float s = row[kk] + spb[(kk - q + S_ - 1) * H_ + h];
            if (masked && ((q < 5) != (kk < 5))) s -= 100.0f;
            row[kk] = s;
        }

        float m = row[0];
        #pragma unroll
        for (int kk = 1; kk < S_; kk++) m = fmaxf(m, row[kk]);
        float sum = 0.0f;
        #pragma unroll
        for (int kk = 0; kk < S_; kk++) { row[kk] = __expf(row[kk] - m); sum += row[kk]; }
        const float inv = 1.0f / sum;

        u64 o2[DH_ / 2];
        #pragma unroll
        for (int dp = 0; dp < DH_ / 2; dp++) o2[dp] = 0ull;
        #pragma unroll
        for (int kk = 0; kk < S_; kk++) {
            const u64 pk = dup2(row[kk]);
            const u64* vr = (const u64*)&sV[(wh * S_ + kk) * DH_];
            #pragma unroll
            for (int dp = 0; dp < DH_ / 2; dp++) o2[dp] = fma2(vr[dp], pk, o2[dp]);
        }

        const int crow = wi * S_ + q;       // flat ctx row 0..39
        #pragma unroll
        for (int dp = 0; dp < DH_ / 2; dp++) {
            float lo, hi; unpack2(o2[dp], lo, hi);
            xt[(h * DH_ + 2 * dp) * XS + crow]     = lo * inv;
            xt[(h * DH_ + 2 * dp + 1) * XS + crow] = hi * inv;
        }
    }
    __syncthreads();

    // ---- phase 3: output projection. thread = 8 adjacent cols x 4 rows (120 thr) ----
    if (tid < 120) {
        const int cg = tid % 12;
        const int rg = tid / 12;           // 0..9
        const int c0 = 8 * cg;
        const int r0 = 4 * rg;

        u64 acc[8][2];
        {
            const float4 bA = *(const float4*)&bo[c0];
            const float4 bB = *(const float4*)&bo[c0 + 4];
            acc[0][0] = acc[0][1] = dup2(bA.x);
            acc[1][0] = acc[1][1] = dup2(bA.y);
            acc[2][0] = acc[2][1] = dup2(bA.z);
            acc[3][0] = acc[3][1] = dup2(bA.w);
            acc[4][0] = acc[4][1] = dup2(bB.x);
            acc[5][0] = acc[5][1] = dup2(bB.y);
            acc[6][0] = acc[6][1] = dup2(bB.z);
            acc[7][0] = acc[7][1] = dup2(bB.w);
        }

        const float* xrow = xt + r0;
        #pragma unroll 2
        for (int k = 0; k < E_; k++) {
            const float4 wA = *(const float4*)&Wo[k * E_ + c0];
            const float4 wB = *(const float4*)&Wo[k * E_ + c0 + 4];
            u64 xa, xb;
            lds_v2u64(xa, xb, xrow + k * XS);
            const u64 w0 = dup2(wA.x), w1 = dup2(wA.y), w2 = dup2(wA.z), w3 = dup2(wA.w);
            const u64 w4 = dup2(wB.x), w5 = dup2(wB.y), w6 = dup2(wB.z), w7 = dup2(wB.w);
            acc[0][0] = fma2(xa, w0, acc[0][0]); acc[0][1] = fma2(xb, w0, acc[0][1]);
            acc[1][0] = fma2(xa, w1, acc[1][0]); acc[1][1] = fma2(xb, w1, acc[1][1]);
            acc[2][0] = fma2(xa, w2, acc[2][0]); acc[2][1] = fma2(xb, w2, acc[2][1]);
            acc[3][0] = fma2(xa, w3, acc[3][0]); acc[3][1] = fma2(xb, w3, acc[3][1]);
            acc[4][0] = fma2(xa, w4, acc[4][0]); acc[4][1] = fma2(xb, w4, acc[4][1]);
            acc[5][0] = fma2(xa, w5, acc[5][0]); acc[5][1] = fma2(xb, w5, acc[5][1]);
            acc[6][0] = fma2(xa, w6, acc[6][0]); acc[6][1] = fma2(xb, w6, acc[6][1]);
            acc[7][0] = fma2(xa, w7, acc[7][0]); acc[7][1] = fma2(xb, w7, acc[7][1]);
        }

        float* gout = out + wbase * (S_ * E_);
        #pragma unroll
        for (int i = 0; i < 4; i++) {
            const int pr = i >> 1;
            float lo, hi;
            float4 oA, oB;
            unpack2(acc[0][pr], lo, hi); oA.x = (i & 1) ? hi : lo;
            unpack2(acc[1][pr], lo, hi); oA.y = (i & 1) ? hi : lo;
            unpack2(acc[2][pr], lo, hi); oA.z = (i & 1) ? hi : lo;
            unpack2(acc[3][pr], lo, hi); oA.w = (i & 1) ? hi : lo;
            unpack2(acc[4][pr], lo, hi); oB.x = (i & 1) ? hi : lo;
            unpack2(acc[5][pr], lo, hi); oB.y = (i & 1) ? hi : lo;
            unpack2(acc[6][pr], lo, hi); oB.z = (i & 1) ? hi : lo;
            unpack2(acc[7][pr], lo, hi); oB.w = (i & 1) ? hi : lo;
            *(float4*)&gout[(r0 + i) * E_ + c0]     = oA;
            *(float4*)&gout[(r0 + i) * E_ + c0 + 4] = oB;
        }
    }
}

extern "C" void kernel_launch(void* const* d_in, const int* in_sizes, int n_in,
                              void* d_out, int out_size)
{
    const float* X    = (const float*)d_in[0];
    const float* Wqkv = (const float*)d_in[1];
    const float* bqkv = (const float*)d_in[2];
    const float* Wo   = (const float*)d_in[3];
    const float* bo   = (const float*)d_in[4];
    const float* posb = (const float*)d_in[5];
    float* out = (float*)d_out;

    const int n_windows = in_sizes[0] / (S_ * E_);   // 65536
    const int grid = n_windows / WPB;                // 16384

    swin_msa_kernel<<<grid, NTHREADS>>>(X, Wqkv, bqkv, Wo, bo, posb, out);
}